// round 16
// baseline (speedup 1.0000x reference)
#include <cuda_runtime.h>
#include <cuda_bf16.h>
#include <cuda_fp16.h>
#include <cstdint>

#define NTOT 16384
#define CIN  256
#define CRD  128
#define KSPLIT 4
#define KEYS_PER_SPLIT (NTOT / KSPLIT)

// scratch (device globals; no allocation allowed)
__device__ __half g_xh[NTOT * CIN];        // x transposed [n][c], fp16
__device__ __half g_whq[CRD * CIN];
__device__ __half g_whk[CRD * CIN];
__device__ __half g_whv[CRD * CIN];
__device__ __half g_who[CIN * CRD];
__device__ __half g_q[NTOT * CRD];
__device__ __half g_k[NTOT * CRD];
__device__ __half g_v[NTOT * CRD];
__device__ float  g_opart[KSPLIT * NTOT * CRD];   // unnormalized partial O
__device__ float  g_lpart[KSPLIT * NTOT];         // partial softmax denominators
__device__ __half g_oh[NTOT * CRD];               // normalized O, fp16 [n][cr]

__device__ __forceinline__ uint32_t smem_to_u32(const void* p) {
    uint32_t a;
    asm("{ .reg .u64 t; cvta.to.shared.u64 t, %1; cvt.u32.u64 %0, t; }"
        : "=r"(a) : "l"(p));
    return a;
}

__device__ __forceinline__ uint32_t pack_h16(float a, float b) {
    __half2 h = __floats2half2_rn(a, b);
    return *reinterpret_cast<uint32_t*>(&h);
}

__device__ __forceinline__ uint32_t h2exp2(uint32_t x) {
    uint32_t y;
    asm("ex2.approx.f16x2 %0, %1;" : "=r"(y) : "r"(x));
    return y;
}

__device__ __forceinline__ uint32_t hadd2(uint32_t a, uint32_t b) {
    uint32_t c;
    asm("add.f16x2 %0, %1, %2;" : "=r"(c) : "r"(a), "r"(b));
    return c;
}

__device__ __forceinline__ float2 h2f2(uint32_t h) {
    __half2 x = *reinterpret_cast<__half2*>(&h);
    return __half22float2(x);
}

__device__ __forceinline__ void mma_f32(float c[4],
    uint32_t a0, uint32_t a1, uint32_t a2, uint32_t a3,
    uint32_t b0, uint32_t b1)
{
    asm volatile(
        "mma.sync.aligned.m16n8k16.row.col.f32.f16.f16.f32 "
        "{%0,%1,%2,%3}, {%4,%5,%6,%7}, {%8,%9}, {%0,%1,%2,%3};\n"
        : "+f"(c[0]), "+f"(c[1]), "+f"(c[2]), "+f"(c[3])
        : "r"(a0), "r"(a1), "r"(a2), "r"(a3), "r"(b0), "r"(b1));
}

__device__ __forceinline__ void mma_f16(uint32_t c[2],
    uint32_t a0, uint32_t a1, uint32_t a2, uint32_t a3,
    uint32_t b0, uint32_t b1)
{
    asm volatile(
        "mma.sync.aligned.m16n8k16.row.col.f16.f16.f16.f16 "
        "{%0,%1}, {%2,%3,%4,%5}, {%6,%7}, {%0,%1};\n"
        : "+r"(c[0]), "+r"(c[1])
        : "r"(a0), "r"(a1), "r"(a2), "r"(a3), "r"(b0), "r"(b1));
}

__device__ __forceinline__ void ldsm4(uint32_t& r0, uint32_t& r1,
                                      uint32_t& r2, uint32_t& r3, uint32_t a) {
    asm volatile("ldmatrix.sync.aligned.m8n8.x4.shared.b16 {%0,%1,%2,%3}, [%4];"
        : "=r"(r0), "=r"(r1), "=r"(r2), "=r"(r3) : "r"(a));
}

__device__ __forceinline__ void ldsm4t(uint32_t& r0, uint32_t& r1,
                                       uint32_t& r2, uint32_t& r3, uint32_t a) {
    asm volatile("ldmatrix.sync.aligned.m8n8.x4.trans.shared.b16 {%0,%1,%2,%3}, [%4];"
        : "=r"(r0), "=r"(r1), "=r"(r2), "=r"(r3) : "r"(a));
}

__device__ __forceinline__ void cp16(uint32_t saddr, const void* g) {
    asm volatile("cp.async.cg.shared.global [%0], [%1], 16;"
        :: "r"(saddr), "l"(g));
}
#define CP_COMMIT() asm volatile("cp.async.commit_group;" ::: "memory")
#define CP_WAIT0()  asm volatile("cp.async.wait_group 0;"  ::: "memory")
#define CP_WAIT1()  asm volatile("cp.async.wait_group 1;"  ::: "memory")

// ===========================================================================
// Kernel 0a: x [c][n] fp32 -> g_xh [n][c] fp16 (transposed)
// ===========================================================================
__global__ __launch_bounds__(256) void convx_kernel(const float* __restrict__ x)
{
    const int n0 = blockIdx.x * 128;
    const int c0 = blockIdx.y * 32;
    const int tid = threadIdx.x;
    __shared__ float Xs[32 * 132];
#pragma unroll
    for (int i = 0; i < 16; i++) {
        int lin = tid + i * 256;
        int r = lin >> 7, n = lin & 127;
        Xs[r * 132 + n] = x[(size_t)(c0 + r) * NTOT + n0 + n];
    }
    __syncthreads();
#pragma unroll
    for (int i = 0; i < 16; i++) {
        int lin = tid + i * 256;
        int n = lin >> 5, c = lin & 31;
        g_xh[(size_t)(n0 + n) * CIN + c0 + c] = __float2half(Xs[c * 132 + n]);
    }
}

// ===========================================================================
// Kernel 0b: weight conversion fp32 -> fp16
// ===========================================================================
__global__ __launch_bounds__(256) void convw_kernel(
    const float* __restrict__ Wq, const float* __restrict__ Wk,
    const float* __restrict__ Wv, const float* __restrict__ Wo)
{
    int e = blockIdx.x * 1024 + threadIdx.x;
#pragma unroll
    for (int i = 0; i < 4; i++, e += 256) {
        int seg = e >> 15;
        int off = e & 32767;
        if (seg == 0)      g_whq[off] = __float2half(Wq[off]);
        else if (seg == 1) g_whk[off] = __float2half(Wk[off]);
        else if (seg == 2) g_whv[off] = __float2half(Wv[off]);
        else               g_who[off] = __float2half(Wo[off]);
    }
}

// ===========================================================================
// Kernel A: q/k/v projection on tensor cores (unchanged).
// ===========================================================================
#define PROW 72

__global__ __launch_bounds__(256) void proj_kernel(
    const float* __restrict__ bq, const float* __restrict__ bk,
    const float* __restrict__ bv)
{
    const int type = blockIdx.y;
    const __half* Wh = (type == 0) ? g_whq : (type == 1) ? g_whk : g_whv;
    const float* bs  = (type == 0) ? bq : (type == 1) ? bk : bv;
    __half* dst = (type == 0) ? g_q : (type == 1) ? g_k : g_v;
    const float scl = (type == 0) ? 0.0625f * 1.4426950408889634f : 1.0f;

    const int n0  = blockIdx.x * 128;
    const int tid = threadIdx.x;
    const int warp = tid >> 5;
    const int lane = tid & 31;
    const int g    = lane >> 2;
    const int tc   = lane & 3;
    const int w    = lane & 7;

    __shared__ __align__(16) __half As[128 * PROW];
    __shared__ __align__(16) __half Bs[128 * PROW];
    const uint32_t sa = smem_to_u32(As);
    const uint32_t sbb = smem_to_u32(Bs);

    const uint32_t a_off = (uint32_t)(w + (lane & 8)) * PROW * 2 + ((lane & 16) >> 1) * 2;
    const uint32_t b_off = ((uint32_t)(w + ((lane & 16) >> 1)) * PROW + (lane & 8)) * 2;

    float acc[16][4];
#pragma unroll
    for (int i = 0; i < 16; i++)
#pragma unroll
        for (int j = 0; j < 4; j++) acc[i][j] = 0.f;

    for (int c0 = 0; c0 < CIN; c0 += 64) {
        __syncthreads();
#pragma unroll
        for (int i = 0; i < 4; i++) {
            int lin = tid + i * 256;
            int r = lin >> 3, kc = (lin & 7) * 8;
            cp16(sa  + (uint32_t)(r * PROW + kc) * 2,
                 g_xh + (size_t)(n0 + r) * CIN + c0 + kc);
            cp16(sbb + (uint32_t)(r * PROW + kc) * 2,
                 Wh + (size_t)r * CIN + c0 + kc);
        }
        CP_COMMIT();
        CP_WAIT0();
        __syncthreads();

#pragma unroll
        for (int kt = 0; kt < 4; kt++) {
            uint32_t a0, a1, a2, a3;
            ldsm4(a0, a1, a2, a3, sa + a_off + (uint32_t)(warp * 16) * PROW * 2 + kt * 32);
#pragma unroll
            for (int np2 = 0; np2 < 8; np2++) {
                uint32_t b0, b1, b2, b3;
                ldsm4(b0, b1, b2, b3, sbb + b_off + (uint32_t)(np2 * 16) * PROW * 2 + kt * 32);
                mma_f32(acc[2 * np2],     a0, a1, a2, a3, b0, b1);
                mma_f32(acc[2 * np2 + 1], a0, a1, a2, a3, b2, b3);
            }
        }
    }

    const int r0 = n0 + warp * 16 + g;
#pragma unroll
    for (int np = 0; np < 16; np++) {
        int col = np * 8 + tc * 2;
        float bb0 = bs[col], bb1 = bs[col + 1];
        uint32_t h0 = pack_h16((acc[np][0] + bb0) * scl, (acc[np][1] + bb1) * scl);
        uint32_t h1 = pack_h16((acc[np][2] + bb0) * scl, (acc[np][3] + bb1) * scl);
        *(uint32_t*)&dst[(size_t)r0 * CRD + col]       = h0;
        *(uint32_t*)&dst[(size_t)(r0 + 8) * CRD + col] = h1;
    }
}

// ===========================================================================
// Kernel B: flash attention, split-KV x4, M=32/warp, 4 warps, all-f16 MMA.
// grid 512 = 128 q-tiles x 4 kv-splits, 128 threads, 2 CTAs/SM.
// No online max: S acc pre-biased to -6; partial O (unnormalized, f32) and
// partial l written per split; combine_kernel normalizes.
// ===========================================================================
#define KROW 136
#define SBUF (64 * KROW * 2)
#define ATTN_SMEM (4 * SBUF)
#define HM6 0xC600C600u               // half2(-6,-6)

__global__ void __launch_bounds__(128, 2) attn_kernel()
{
    extern __shared__ __align__(16) char smem[];
    const uint32_t sb = smem_to_u32(smem);
    const int tid   = threadIdx.x;
    const int warp  = tid >> 5;
    const int lane  = tid & 31;
    const int g     = lane >> 2;
    const int tc    = lane & 3;
    const int w     = lane & 7;
    const int qt    = blockIdx.x >> 2;
    const int split = blockIdx.x & 3;
    const int q0    = qt * 128;
    const int kbase = split * KEYS_PER_SPLIT;

    const uint32_t qk_koff = ((uint32_t)(w + ((lane & 16) >> 1)) * KROW + (lane & 8)) * 2;
    const uint32_t tr_off  = (uint32_t)(w + (lane & 8)) * KROW * 2 + ((lane & 16) >> 1) * 2;

    // ---- stage Q (128 rows) into K0+K1 area, pull fragments (M=32/warp)
#pragma unroll
    for (int i = 0; i < 16; i++) {
        int c = tid + i * 128;
        int row = c >> 4, col = (c & 15) * 8;
        *(uint4*)(smem + (row * KROW + col) * 2) =
            *(const uint4*)(g_q + (size_t)(q0 + row) * CRD + col);
    }
    __syncthreads();
    uint32_t qf[8][2][4];
#pragma unroll
    for (int mt = 0; mt < 2; mt++) {
        const uint32_t qbase = sb + tr_off + (uint32_t)(warp * 32 + mt * 16) * KROW * 2;
#pragma unroll
        for (int kt = 0; kt < 8; kt++)
            ldsm4(qf[kt][mt][0], qf[kt][mt][1], qf[kt][mt][2], qf[kt][mt][3],
                  qbase + kt * 32);
    }
    __syncthreads();

    // ---- prologue: async-load tiles 0 and 1
#pragma unroll
    for (int pit = 0; pit < 2; pit++) {
        const int kv0 = kbase + pit * 64;
        const uint32_t kb = sb + pit * SBUF;
        const uint32_t vb = sb + 2 * SBUF + pit * SBUF;
#pragma unroll
        for (int i = 0; i < 8; i++) {
            int c = tid + i * 128;
            int row = c >> 4, col = (c & 15) * 8;
            uint32_t so = (uint32_t)(row * KROW + col) * 2;
            cp16(kb + so, g_k + (size_t)(kv0 + row) * CRD + col);
            cp16(vb + so, g_v + (size_t)(kv0 + row) * CRD + col);
        }
        CP_COMMIT();
    }

    uint32_t oa[2][16][2];
#pragma unroll
    for (int mt = 0; mt < 2; mt++)
#pragma unroll
        for (int n = 0; n < 16; n++) { oa[mt][n][0] = 0u; oa[mt][n][1] = 0u; }
    float lac[2][2] = {{0.f, 0.f}, {0.f, 0.f}};

    const int NIT = KEYS_PER_SPLIT / 64;   // 64
    for (int it = 0; it < NIT; ++it) {
        const int b = it & 1;
        CP_WAIT1();
        __syncthreads();
        const uint32_t kb = sb + b * SBUF;
        const uint32_t vb = sb + 2 * SBUF + b * SBUF;

        // ---- S = Q K^T in fp16 (pre-biased -6); M=32 per warp
        uint32_t sc[2][8][2];
#pragma unroll
        for (int mt = 0; mt < 2; mt++)
#pragma unroll
            for (int n = 0; n < 8; n++) { sc[mt][n][0] = HM6; sc[mt][n][1] = HM6; }
#pragma unroll
        for (int kt = 0; kt < 8; kt++) {
            const uint32_t ka = kb + qk_koff + kt * 32;
#pragma unroll
            for (int np = 0; np < 4; np++) {
                uint32_t b0, b1, b2, b3;
                ldsm4(b0, b1, b2, b3, ka + np * (16 * KROW * 2));
#pragma unroll
                for (int mt = 0; mt < 2; mt++) {
                    mma_f16(sc[mt][2 * np],
                            qf[kt][mt][0], qf[kt][mt][1], qf[kt][mt][2], qf[kt][mt][3],
                            b0, b1);
                    mma_f16(sc[mt][2 * np + 1],
                            qf[kt][mt][0], qf[kt][mt][1], qf[kt][mt][2], qf[kt][mt][3],
                            b2, b3);
                }
            }
        }

        // ---- P = 2^(S-6) in place; sc becomes the PV A-fragments
#pragma unroll
        for (int mt = 0; mt < 2; mt++) {
            uint32_t s0 = 0u, s1 = 0u;
#pragma unroll
            for (int n = 0; n < 8; n++) {
                sc[mt][n][0] = h2exp2(sc[mt][n][0]);
                sc[mt][n][1] = h2exp2(sc[mt][n][1]);
                s0 = hadd2(s0, sc[mt][n][0]);
                s1 = hadd2(s1, sc[mt][n][1]);
            }
            float2 f0 = h2f2(s0);
            float2 f1 = h2f2(s1);
            lac[mt][0] += f0.x + f0.y;
            lac[mt][1] += f1.x + f1.y;
        }

        // ---- O += P V, fp16 accumulation
#pragma unroll
        for (int np = 0; np < 4; np++) {
            const uint32_t va = vb + tr_off + np * (16 * KROW * 2);
#pragma unroll
            for (int dp = 0; dp < 8; dp++) {
                uint32_t b0, b1, b2, b3;
                ldsm4t(b0, b1, b2, b3, va + dp * 32);
#pragma unroll
                for (int mt = 0; mt < 2; mt++) {
                    mma_f16(oa[mt][2 * dp],
                            sc[mt][2 * np][0], sc[mt][2 * np][1],
                            sc[mt][2 * np + 1][0], sc[mt][2 * np + 1][1],
                            b0, b1);
                    mma_f16(oa[mt][2 * dp + 1],
                            sc[mt][2 * np][0], sc[mt][2 * np][1],
                            sc[mt][2 * np + 1][0], sc[mt][2 * np + 1][1],
                            b2, b3);
                }
            }
        }

        __syncthreads();
        if (it + 2 < NIT) {
            const int kv0 = kbase + (it + 2) * 64;
#pragma unroll
            for (int i = 0; i < 8; i++) {
                int c = tid + i * 128;
                int row = c >> 4, col = (c & 15) * 8;
                uint32_t so = (uint32_t)(row * KROW + col) * 2;
                cp16(kb + so, g_k + (size_t)(kv0 + row) * CRD + col);
                cp16(vb + so, g_v + (size_t)(kv0 + row) * CRD + col);
            }
        }
        CP_COMMIT();
    }

    // ---- epilogue: write unnormalized partial O (f32) and partial l
    const size_t ob = (size_t)split * NTOT * CRD;
#pragma unroll
    for (int mt = 0; mt < 2; mt++) {
        float l0 = lac[mt][0], l1 = lac[mt][1];
        l0 += __shfl_xor_sync(0xffffffffu, l0, 1);
        l0 += __shfl_xor_sync(0xffffffffu, l0, 2);
        l1 += __shfl_xor_sync(0xffffffffu, l1, 1);
        l1 += __shfl_xor_sync(0xffffffffu, l1, 2);
        const int r0 = q0 + warp * 32 + mt * 16 + g;
#pragma unroll
        for (int n = 0; n < 16; n++) {
            int col = n * 8 + tc * 2;
            float2 v0 = h2f2(oa[mt][n][0]);
            float2 v1 = h2f2(oa[mt][n][1]);
            *(float2*)&g_opart[ob + (size_t)r0 * CRD + col]       = v0;
            *(float2*)&g_opart[ob + (size_t)(r0 + 8) * CRD + col] = v1;
        }
        if (tc == 0) {
            g_lpart[split * NTOT + r0]     = l0;
            g_lpart[split * NTOT + r0 + 8] = l1;
        }
    }
}

// ===========================================================================
// Kernel B2: combine split-KV partials -> normalized fp16 O.
// grid 1024 x 256 threads: block = 16 rows, thread = 8 dims of one row.
// ===========================================================================
__global__ __launch_bounds__(256) void combine_kernel()
{
    const int t   = threadIdx.x;
    const int row = blockIdx.x * 16 + (t >> 4);
    const int d0  = (t & 15) * 8;

    float l = 0.f;
#pragma unroll
    for (int s = 0; s < KSPLIT; s++) l += g_lpart[s * NTOT + row];
    const float inv = 1.0f / l;

    float acc[8];
#pragma unroll
    for (int j = 0; j < 8; j++) acc[j] = 0.f;
#pragma unroll
    for (int s = 0; s < KSPLIT; s++) {
        const float* p = g_opart + (size_t)s * NTOT * CRD + (size_t)row * CRD + d0;
        float4 a = *(const float4*)p;
        float4 b = *(const float4*)(p + 4);
        acc[0] += a.x; acc[1] += a.y; acc[2] += a.z; acc[3] += a.w;
        acc[4] += b.x; acc[5] += b.y; acc[6] += b.z; acc[7] += b.w;
    }
    uint4 pk;
    pk.x = pack_h16(acc[0] * inv, acc[1] * inv);
    pk.y = pack_h16(acc[2] * inv, acc[3] * inv);
    pk.z = pack_h16(acc[4] * inv, acc[5] * inv);
    pk.w = pack_h16(acc[6] * inv, acc[7] * inv);
    *(uint4*)&g_oh[(size_t)row * CRD + d0] = pk;
}

// ===========================================================================
// Kernel C: outproj on tensor cores (unchanged).
// ===========================================================================
#define OP_O   0
#define OP_W   (128 * KROW * 2)
#define OP_T   (OP_W + 64 * KROW * 2)
#define OP_SMEM (OP_T + 64 * 132 * 4)

__global__ __launch_bounds__(256) void outproj_kernel(
    const float* __restrict__ x,
    const float* __restrict__ bo,
    float* __restrict__ out)
{
    extern __shared__ __align__(16) char smem[];
    const uint32_t sb = smem_to_u32(smem);
    const int n0  = blockIdx.x * 128;
    const int ocb = blockIdx.y * 64;
    const int tid = threadIdx.x;
    const int warp = tid >> 5;
    const int lane = tid & 31;
    const int g    = lane >> 2;
    const int tc   = lane & 3;
    const int w    = lane & 7;

    const uint32_t a_off = (uint32_t)(w + (lane & 8)) * KROW * 2 + ((lane & 16) >> 1) * 2;
    const uint32_t b_off = ((uint32_t)(w + ((lane & 16) >> 1)) * KROW + (lane & 8)) * 2;

#pragma unroll
    for (int i = 0; i < 8; i++) {
        int c = tid + i * 256;
        int row = c >> 4, col = (c & 15) * 8;
        cp16(sb + OP_O + (uint32_t)(row * KROW + col) * 2,
             g_oh + (size_t)(n0 + row) * CRD + col);
    }
#pragma unroll
    for (int i = 0; i < 4; i++) {
        int c = tid + i * 256;
        int row = c >> 4, col = (c & 15) * 8;
        cp16(sb + OP_W + (uint32_t)(row * KROW + col) * 2,
             g_who + (size_t)(ocb + row) * CRD + col);
    }
    CP_COMMIT();
    CP_WAIT0();
    __syncthreads();

    float acc[8][4];
#pragma unroll
    for (int i = 0; i < 8; i++)
#pragma unroll
        for (int j = 0; j < 4; j++) acc[i][j] = 0.f;

#pragma unroll
    for (int kt = 0; kt < 8; kt++) {
        uint32_t a0, a1, a2, a3;
        ldsm4(a0, a1, a2, a3,
              sb + OP_O + a_off + (uint32_t)(warp * 16) * KROW * 2 + kt * 32);
#pragma unroll
        for (int np2 = 0; np2 < 4; np2++) {
            uint32_t b0, b1, b2, b3;
            ldsm4(b0, b1, b2, b3,
                  sb + OP_W + b_off + (uint32_t)(np2 * 16) * KROW * 2 + kt * 32);
            mma_f32(acc[2 * np2],     a0, a1, a2, a3, b0, b1);
            mma_f32(acc[2 * np2 + 1], a0, a1, a2, a3, b2, b3);
        }
    }

    float* Tt = (float*)(smem + OP_T);
    const int nloc = warp * 16 + g;
#pragma unroll
    for (int np = 0; np < 8; np++) {
        int col = np * 8 + tc * 2;
        Tt[col * 132 + nloc]             = acc[np][0];
        Tt[(col + 1) * 132 + nloc]       = acc[np][1];
        Tt[col * 132 + nloc + 8]         = acc[np][2];
        Tt[(col + 1) * 132 + nloc + 8]   = acc[np][3];
    }
    __syncthreads();

#pragma unroll
    for (int i = 0; i < 32; i++) {
        int lin = tid + i * 256;
        int c = lin >> 7, n = lin & 127;
        size_t base = (size_t)(ocb + c) * NTOT + n0 + n;
        out[base] = x[base] + bo[ocb + c] + Tt[c * 132 + n];
    }
}

// ===========================================================================
extern "C" void kernel_launch(void* const* d_in, const int* in_sizes, int n_in,
                              void* d_out, int out_size)
{
    (void)in_sizes; (void)n_in; (void)out_size;
    const float* x  = (const float*)d_in[0];
    const float* Wq = (const float*)d_in[1];
    const float* bq = (const float*)d_in[2];
    const float* Wk = (const float*)d_in[3];
    const float* bk = (const float*)d_in[4];
    const float* Wv = (const float*)d_in[5];
    const float* bv = (const float*)d_in[6];
    const float* Wo = (const float*)d_in[7];
    const float* bo = (const float*)d_in[8];
    float* out = (float*)d_out;

    cudaFuncSetAttribute(attn_kernel,
                         cudaFuncAttributeMaxDynamicSharedMemorySize, ATTN_SMEM);
    cudaFuncSetAttribute(outproj_kernel,
                         cudaFuncAttributeMaxDynamicSharedMemorySize, OP_SMEM);

    dim3 gX(NTOT / 128, CIN / 32);
    convx_kernel<<<gX, 256>>>(x);
    convw_kernel<<<128, 256>>>(Wq, Wk, Wv, Wo);

    dim3 gA(NTOT / 128, 3);
    proj_kernel<<<gA, 256>>>(bq, bk, bv);

    attn_kernel<<<(NTOT / 128) * KSPLIT, 128, ATTN_SMEM>>>();
    combine_kernel<<<NTOT / 16, 256>>>();

    dim3 gC(NTOT / 128, CIN / 64);
    outproj_kernel<<<gC, 256, OP_SMEM>>>(x, bo, out);
}

// round 17
// speedup vs baseline: 1.2764x; 1.2764x over previous
#include <cuda_runtime.h>
#include <cuda_bf16.h>
#include <cuda_fp16.h>
#include <cstdint>

#define NTOT 16384
#define CIN  256
#define CRD  128

// scratch (device globals; no allocation allowed)
__device__ __half g_xh[NTOT * CIN];        // x transposed [n][c], fp16
__device__ __half g_whq[CRD * CIN];
__device__ __half g_whk[CRD * CIN];
__device__ __half g_whv[CRD * CIN];
__device__ __half g_who[CIN * CRD];
__device__ __half g_q[NTOT * CRD];
__device__ __half g_k[NTOT * CRD];
__device__ __half g_v[NTOT * CRD];
__device__ __half g_oh[NTOT * CRD];        // attention output, fp16 [n][cr]

__device__ __forceinline__ uint32_t smem_to_u32(const void* p) {
    uint32_t a;
    asm("{ .reg .u64 t; cvta.to.shared.u64 t, %1; cvt.u32.u64 %0, t; }"
        : "=r"(a) : "l"(p));
    return a;
}

__device__ __forceinline__ uint32_t pack_h16(float a, float b) {
    __half2 h = __floats2half2_rn(a, b);
    return *reinterpret_cast<uint32_t*>(&h);
}

__device__ __forceinline__ float ex2(float x) {
    float y;
    asm("ex2.approx.f32 %0, %1;" : "=f"(y) : "f"(x));
    return y;
}

// fp16 in / fp32 accum (all GEMMs: f32 accumulate is the fast path on sm_103a)
__device__ __forceinline__ void mma_f32(float c[4],
    uint32_t a0, uint32_t a1, uint32_t a2, uint32_t a3,
    uint32_t b0, uint32_t b1)
{
    asm volatile(
        "mma.sync.aligned.m16n8k16.row.col.f32.f16.f16.f32 "
        "{%0,%1,%2,%3}, {%4,%5,%6,%7}, {%8,%9}, {%0,%1,%2,%3};\n"
        : "+f"(c[0]), "+f"(c[1]), "+f"(c[2]), "+f"(c[3])
        : "r"(a0), "r"(a1), "r"(a2), "r"(a3), "r"(b0), "r"(b1));
}

__device__ __forceinline__ void ldsm4(uint32_t& r0, uint32_t& r1,
                                      uint32_t& r2, uint32_t& r3, uint32_t a) {
    asm volatile("ldmatrix.sync.aligned.m8n8.x4.shared.b16 {%0,%1,%2,%3}, [%4];"
        : "=r"(r0), "=r"(r1), "=r"(r2), "=r"(r3) : "r"(a));
}

__device__ __forceinline__ void ldsm4t(uint32_t& r0, uint32_t& r1,
                                       uint32_t& r2, uint32_t& r3, uint32_t a) {
    asm volatile("ldmatrix.sync.aligned.m8n8.x4.trans.shared.b16 {%0,%1,%2,%3}, [%4];"
        : "=r"(r0), "=r"(r1), "=r"(r2), "=r"(r3) : "r"(a));
}

__device__ __forceinline__ void cp16(uint32_t saddr, const void* g) {
    asm volatile("cp.async.cg.shared.global [%0], [%1], 16;"
        :: "r"(saddr), "l"(g));
}
#define CP_COMMIT() asm volatile("cp.async.commit_group;" ::: "memory")
#define CP_WAIT0()  asm volatile("cp.async.wait_group 0;"  ::: "memory")
#define CP_WAIT1()  asm volatile("cp.async.wait_group 1;"  ::: "memory")

// ===========================================================================
// Kernel 0a: x [c][n] fp32 -> g_xh [n][c] fp16 (transposed)
// ===========================================================================
__global__ __launch_bounds__(256) void convx_kernel(const float* __restrict__ x)
{
    const int n0 = blockIdx.x * 128;
    const int c0 = blockIdx.y * 32;
    const int tid = threadIdx.x;
    __shared__ float Xs[32 * 132];
#pragma unroll
    for (int i = 0; i < 16; i++) {
        int lin = tid + i * 256;
        int r = lin >> 7, n = lin & 127;
        Xs[r * 132 + n] = x[(size_t)(c0 + r) * NTOT + n0 + n];
    }
    __syncthreads();
#pragma unroll
    for (int i = 0; i < 16; i++) {
        int lin = tid + i * 256;
        int n = lin >> 5, c = lin & 31;
        g_xh[(size_t)(n0 + n) * CIN + c0 + c] = __float2half(Xs[c * 132 + n]);
    }
}

// ===========================================================================
// Kernel 0b: weight conversion fp32 -> fp16
// ===========================================================================
__global__ __launch_bounds__(256) void convw_kernel(
    const float* __restrict__ Wq, const float* __restrict__ Wk,
    const float* __restrict__ Wv, const float* __restrict__ Wo)
{
    int e = blockIdx.x * 1024 + threadIdx.x;
#pragma unroll
    for (int i = 0; i < 4; i++, e += 256) {
        int seg = e >> 15;
        int off = e & 32767;
        if (seg == 0)      g_whq[off] = __float2half(Wq[off]);
        else if (seg == 1) g_whk[off] = __float2half(Wk[off]);
        else if (seg == 2) g_whv[off] = __float2half(Wv[off]);
        else               g_who[off] = __float2half(Wo[off]);
    }
}

// ===========================================================================
// Kernel A: q/k/v projection on tensor cores (unchanged).
// ===========================================================================
#define PROW 72

__global__ __launch_bounds__(256) void proj_kernel(
    const float* __restrict__ bq, const float* __restrict__ bk,
    const float* __restrict__ bv)
{
    const int type = blockIdx.y;
    const __half* Wh = (type == 0) ? g_whq : (type == 1) ? g_whk : g_whv;
    const float* bs  = (type == 0) ? bq : (type == 1) ? bk : bv;
    __half* dst = (type == 0) ? g_q : (type == 1) ? g_k : g_v;
    const float scl = (type == 0) ? 0.0625f * 1.4426950408889634f : 1.0f;

    const int n0  = blockIdx.x * 128;
    const int tid = threadIdx.x;
    const int warp = tid >> 5;
    const int lane = tid & 31;
    const int g    = lane >> 2;
    const int tc   = lane & 3;
    const int w    = lane & 7;

    __shared__ __align__(16) __half As[128 * PROW];
    __shared__ __align__(16) __half Bs[128 * PROW];
    const uint32_t sa = smem_to_u32(As);
    const uint32_t sbb = smem_to_u32(Bs);

    const uint32_t a_off = (uint32_t)(w + (lane & 8)) * PROW * 2 + ((lane & 16) >> 1) * 2;
    const uint32_t b_off = ((uint32_t)(w + ((lane & 16) >> 1)) * PROW + (lane & 8)) * 2;

    float acc[16][4];
#pragma unroll
    for (int i = 0; i < 16; i++)
#pragma unroll
        for (int j = 0; j < 4; j++) acc[i][j] = 0.f;

    for (int c0 = 0; c0 < CIN; c0 += 64) {
        __syncthreads();
#pragma unroll
        for (int i = 0; i < 4; i++) {
            int lin = tid + i * 256;
            int r = lin >> 3, kc = (lin & 7) * 8;
            cp16(sa  + (uint32_t)(r * PROW + kc) * 2,
                 g_xh + (size_t)(n0 + r) * CIN + c0 + kc);
            cp16(sbb + (uint32_t)(r * PROW + kc) * 2,
                 Wh + (size_t)r * CIN + c0 + kc);
        }
        CP_COMMIT();
        CP_WAIT0();
        __syncthreads();

#pragma unroll
        for (int kt = 0; kt < 4; kt++) {
            uint32_t a0, a1, a2, a3;
            ldsm4(a0, a1, a2, a3, sa + a_off + (uint32_t)(warp * 16) * PROW * 2 + kt * 32);
#pragma unroll
            for (int np2 = 0; np2 < 8; np2++) {
                uint32_t b0, b1, b2, b3;
                ldsm4(b0, b1, b2, b3, sbb + b_off + (uint32_t)(np2 * 16) * PROW * 2 + kt * 32);
                mma_f32(acc[2 * np2],     a0, a1, a2, a3, b0, b1);
                mma_f32(acc[2 * np2 + 1], a0, a1, a2, a3, b2, b3);
            }
        }
    }

    const int r0 = n0 + warp * 16 + g;
#pragma unroll
    for (int np = 0; np < 16; np++) {
        int col = np * 8 + tc * 2;
        float bb0 = bs[col], bb1 = bs[col + 1];
        uint32_t h0 = pack_h16((acc[np][0] + bb0) * scl, (acc[np][1] + bb1) * scl);
        uint32_t h1 = pack_h16((acc[np][2] + bb0) * scl, (acc[np][3] + bb1) * scl);
        *(uint32_t*)&dst[(size_t)r0 * CRD + col]       = h0;
        *(uint32_t*)&dst[(size_t)(r0 + 8) * CRD + col] = h1;
    }
}

// ===========================================================================
// Kernel B: flash attention. BM=64 (16 rows/warp), 128 threads, 3 CTAs/SM.
// All-f32 MMA accumulation (the fast HMMA path on sm_103a); f32 ex2 softmax,
// no online max (logits bounded, log2e folded into q).
// ===========================================================================
#define KROW 136                         // fp16 elems per smem row (272 B)
#define SBUF (64 * KROW * 2)             // one 64x128 tile buffer (17408 B)
#define ATTN_SMEM (4 * SBUF)             // K0 K1 V0 V1  (69632 B; 3 CTAs/SM)

__global__ void __launch_bounds__(128, 3) attn_kernel()
{
    extern __shared__ __align__(16) char smem[];
    const uint32_t sb = smem_to_u32(smem);
    const int tid  = threadIdx.x;
    const int warp = tid >> 5;
    const int lane = tid & 31;
    const int g    = lane >> 2;
    const int tc   = lane & 3;
    const int q0   = blockIdx.x * 64;
    const int w    = lane & 7;

    const uint32_t qk_koff = ((uint32_t)(w + ((lane & 16) >> 1)) * KROW + (lane & 8)) * 2;
    const uint32_t tr_off  = (uint32_t)(w + (lane & 8)) * KROW * 2 + ((lane & 16) >> 1) * 2;

    // ---- stage Q into buffer 0, pull A-fragments into registers
#pragma unroll
    for (int i = 0; i < 8; i++) {
        int c = tid + i * 128;
        int row = c >> 4, col = (c & 15) * 8;
        *(uint4*)(smem + (row * KROW + col) * 2) =
            *(const uint4*)(g_q + (size_t)(q0 + row) * CRD + col);
    }
    __syncthreads();
    uint32_t qf[8][4];
    {
        const uint32_t qbase = sb + tr_off + (uint32_t)(warp * 16) * KROW * 2;
#pragma unroll
        for (int kt = 0; kt < 8; kt++)
            ldsm4(qf[kt][0], qf[kt][1], qf[kt][2], qf[kt][3], qbase + kt * 32);
    }
    __syncthreads();

    // ---- prologue: async-load tiles 0 and 1
#pragma unroll
    for (int pit = 0; pit < 2; pit++) {
        const int kv0 = pit * 64;
        const uint32_t kb = sb + pit * SBUF;
        const uint32_t vb = sb + 2 * SBUF + pit * SBUF;
#pragma unroll
        for (int i = 0; i < 8; i++) {
            int c = tid + i * 128;
            int row = c >> 4, col = (c & 15) * 8;
            uint32_t so = (uint32_t)(row * KROW + col) * 2;
            cp16(kb + so, g_k + (size_t)(kv0 + row) * CRD + col);
            cp16(vb + so, g_v + (size_t)(kv0 + row) * CRD + col);
        }
        CP_COMMIT();
    }

    float oa[16][4];
#pragma unroll
    for (int j = 0; j < 16; j++)
#pragma unroll
        for (int r = 0; r < 4; r++) oa[j][r] = 0.f;
    float l0 = 0.f, l1 = 0.f;

    for (int it = 0; it < NTOT / 64; ++it) {
        const int b = it & 1;
        CP_WAIT1();
        __syncthreads();
        const uint32_t kb = sb + b * SBUF;
        const uint32_t vb = sb + 2 * SBUF + b * SBUF;

        // ---- S = Q K^T (f32 accum), 16 x 64 per warp
        float sa[8][4];
#pragma unroll
        for (int n = 0; n < 8; n++)
#pragma unroll
            for (int r = 0; r < 4; r++) sa[n][r] = 0.f;
#pragma unroll
        for (int kt = 0; kt < 8; kt++) {
            const uint32_t ka = kb + qk_koff + kt * 32;
#pragma unroll
            for (int np = 0; np < 4; np++) {
                uint32_t b0, b1, b2, b3;
                ldsm4(b0, b1, b2, b3, ka + np * (16 * KROW * 2));
                mma_f32(sa[2 * np],     qf[kt][0], qf[kt][1], qf[kt][2], qf[kt][3], b0, b1);
                mma_f32(sa[2 * np + 1], qf[kt][0], qf[kt][1], qf[kt][2], qf[kt][3], b2, b3);
            }
        }

        // ---- softmax (no rescale): P = 2^S, pack to fp16 PV A-fragments
        uint32_t pa[4][4];
#pragma unroll
        for (int t = 0; t < 4; t++) {
            float p00 = ex2(sa[2 * t][0]);
            float p01 = ex2(sa[2 * t][1]);
            float p02 = ex2(sa[2 * t][2]);
            float p03 = ex2(sa[2 * t][3]);
            float p10 = ex2(sa[2 * t + 1][0]);
            float p11 = ex2(sa[2 * t + 1][1]);
            float p12 = ex2(sa[2 * t + 1][2]);
            float p13 = ex2(sa[2 * t + 1][3]);
            l0 += p00 + p01 + p10 + p11;
            l1 += p02 + p03 + p12 + p13;
            pa[t][0] = pack_h16(p00, p01);
            pa[t][1] = pack_h16(p02, p03);
            pa[t][2] = pack_h16(p10, p11);
            pa[t][3] = pack_h16(p12, p13);
        }

        // ---- O += P V  (f32 accum; V fragments via ldmatrix.trans)
#pragma unroll
        for (int np = 0; np < 4; np++) {
            const uint32_t va = vb + tr_off + np * (16 * KROW * 2);
#pragma unroll
            for (int dp = 0; dp < 8; dp++) {
                uint32_t b0, b1, b2, b3;
                ldsm4t(b0, b1, b2, b3, va + dp * 32);
                mma_f32(oa[2 * dp],     pa[np][0], pa[np][1], pa[np][2], pa[np][3], b0, b1);
                mma_f32(oa[2 * dp + 1], pa[np][0], pa[np][1], pa[np][2], pa[np][3], b2, b3);
            }
        }

        __syncthreads();
        // ---- prefetch tile it+2 into buffer b
        if (it + 2 < NTOT / 64) {
            const int kv0 = (it + 2) * 64;
#pragma unroll
            for (int i = 0; i < 8; i++) {
                int c = tid + i * 128;
                int row = c >> 4, col = (c & 15) * 8;
                uint32_t so = (uint32_t)(row * KROW + col) * 2;
                cp16(kb + so, g_k + (size_t)(kv0 + row) * CRD + col);
                cp16(vb + so, g_v + (size_t)(kv0 + row) * CRD + col);
            }
        }
        CP_COMMIT();
    }

    // ---- epilogue: reduce l across the quad, normalize, store fp16 O
    l0 += __shfl_xor_sync(0xffffffffu, l0, 1);
    l0 += __shfl_xor_sync(0xffffffffu, l0, 2);
    l1 += __shfl_xor_sync(0xffffffffu, l1, 1);
    l1 += __shfl_xor_sync(0xffffffffu, l1, 2);
    const float inv0 = 1.0f / l0;
    const float inv1 = 1.0f / l1;
    const int r0 = q0 + warp * 16 + g;
#pragma unroll
    for (int j = 0; j < 16; j++) {
        int col = j * 8 + tc * 2;
        uint32_t h0 = pack_h16(oa[j][0] * inv0, oa[j][1] * inv0);
        uint32_t h1 = pack_h16(oa[j][2] * inv1, oa[j][3] * inv1);
        *(uint32_t*)&g_oh[(size_t)r0 * CRD + col]       = h0;
        *(uint32_t*)&g_oh[(size_t)(r0 + 8) * CRD + col] = h1;
    }
}

// ===========================================================================
// Kernel C: outproj on tensor cores (unchanged).
// ===========================================================================
#define OP_O   0
#define OP_W   (128 * KROW * 2)
#define OP_T   (OP_W + 64 * KROW * 2)
#define OP_SMEM (OP_T + 64 * 132 * 4)

__global__ __launch_bounds__(256) void outproj_kernel(
    const float* __restrict__ x,
    const float* __restrict__ bo,
    float* __restrict__ out)
{
    extern __shared__ __align__(16) char smem[];
    const uint32_t sb = smem_to_u32(smem);
    const int n0  = blockIdx.x * 128;
    const int ocb = blockIdx.y * 64;
    const int tid = threadIdx.x;
    const int warp = tid >> 5;
    const int lane = tid & 31;
    const int g    = lane >> 2;
    const int tc   = lane & 3;
    const int w    = lane & 7;

    const uint32_t a_off = (uint32_t)(w + (lane & 8)) * KROW * 2 + ((lane & 16) >> 1) * 2;
    const uint32_t b_off = ((uint32_t)(w + ((lane & 16) >> 1)) * KROW + (lane & 8)) * 2;

#pragma unroll
    for (int i = 0; i < 8; i++) {
        int c = tid + i * 256;
        int row = c >> 4, col = (c & 15) * 8;
        cp16(sb + OP_O + (uint32_t)(row * KROW + col) * 2,
             g_oh + (size_t)(n0 + row) * CRD + col);
    }
#pragma unroll
    for (int i = 0; i < 4; i++) {
        int c = tid + i * 256;
        int row = c >> 4, col = (c & 15) * 8;
        cp16(sb + OP_W + (uint32_t)(row * KROW + col) * 2,
             g_who + (size_t)(ocb + row) * CRD + col);
    }
    CP_COMMIT();
    CP_WAIT0();
    __syncthreads();

    float acc[8][4];
#pragma unroll
    for (int i = 0; i < 8; i++)
#pragma unroll
        for (int j = 0; j < 4; j++) acc[i][j] = 0.f;

#pragma unroll
    for (int kt = 0; kt < 8; kt++) {
        uint32_t a0, a1, a2, a3;
        ldsm4(a0, a1, a2, a3,
              sb + OP_O + a_off + (uint32_t)(warp * 16) * KROW * 2 + kt * 32);
#pragma unroll
        for (int np2 = 0; np2 < 4; np2++) {
            uint32_t b0, b1, b2, b3;
            ldsm4(b0, b1, b2, b3,
                  sb + OP_W + b_off + (uint32_t)(np2 * 16) * KROW * 2 + kt * 32);
            mma_f32(acc[2 * np2],     a0, a1, a2, a3, b0, b1);
            mma_f32(acc[2 * np2 + 1], a0, a1, a2, a3, b2, b3);
        }
    }

    float* Tt = (float*)(smem + OP_T);
    const int nloc = warp * 16 + g;
#pragma unroll
    for (int np = 0; np < 8; np++) {
        int col = np * 8 + tc * 2;
        Tt[col * 132 + nloc]             = acc[np][0];
        Tt[(col + 1) * 132 + nloc]       = acc[np][1];
        Tt[col * 132 + nloc + 8]         = acc[np][2];
        Tt[(col + 1) * 132 + nloc + 8]   = acc[np][3];
    }
    __syncthreads();

#pragma unroll
    for (int i = 0; i < 32; i++) {
        int lin = tid + i * 256;
        int c = lin >> 7, n = lin & 127;
        size_t base = (size_t)(ocb + c) * NTOT + n0 + n;
        out[base] = x[base] + bo[ocb + c] + Tt[c * 132 + n];
    }
}

// ===========================================================================
extern "C" void kernel_launch(void* const* d_in, const int* in_sizes, int n_in,
                              void* d_out, int out_size)
{
    (void)in_sizes; (void)n_in; (void)out_size;
    const float* x  = (const float*)d_in[0];
    const float* Wq = (const float*)d_in[1];
    const float* bq = (const float*)d_in[2];
    const float* Wk = (const float*)d_in[3];
    const float* bk = (const float*)d_in[4];
    const float* Wv = (const float*)d_in[5];
    const float* bv = (const float*)d_in[6];
    const float* Wo = (const float*)d_in[7];
    const float* bo = (const float*)d_in[8];
    float* out = (float*)d_out;

    cudaFuncSetAttribute(attn_kernel,
                         cudaFuncAttributeMaxDynamicSharedMemorySize, ATTN_SMEM);
    cudaFuncSetAttribute(outproj_kernel,
                         cudaFuncAttributeMaxDynamicSharedMemorySize, OP_SMEM);

    dim3 gX(NTOT / 128, CIN / 32);
    convx_kernel<<<gX, 256>>>(x);
    convw_kernel<<<128, 256>>>(Wq, Wk, Wv, Wo);

    dim3 gA(NTOT / 128, 3);
    proj_kernel<<<gA, 256>>>(bq, bk, bv);

    attn_kernel<<<NTOT / 64, 128, ATTN_SMEM>>>();

    dim3 gC(NTOT / 128, CIN / 64);
    outproj_kernel<<<gC, 256, OP_SMEM>>>(x, bo, out);
}